// round 16
// baseline (speedup 1.0000x reference)
#include <cuda_runtime.h>
#include <cuda_bf16.h>
#include <cuda_fp16.h>
#include <math.h>
#include <stdint.h>

#define S  2048
#define H  1024
#define NH 16
#define DH 64
#define FF 4096
#define NLAYERS 6
#define VPAD 50432     // 50257 padded to multiple of 128

#define SZ_SH (S*H)

// ---------------- device scratch ----------------
__device__ __align__(16) float g_x[SZ_SH];
__device__ __align__(16) float g_tmp[SZ_SH];
__device__ __align__(16) float g_res[SZ_SH];
__device__ __align__(16) float g_v[SZ_SH];
__device__ __align__(16) float g_part[32*1024];     // V column sums per 64-row block
__device__ __align__(16) float g_s[S*NH];           // s[t,h] scores for last row
__device__ __align__(16) float g_wt[NH*H];          // w~ = Wk @ q_last per head
__device__ __align__(16) float g_alast[NH*DH];      // attn row S-1 (scaled)
__device__ __align__(16) float g_zb[8192];          // zero bias (never written)

// activation hi/lo
__device__ __align__(128) __nv_bfloat16 g_ahi[S*FF];
__device__ __align__(128) __nv_bfloat16 g_alo[S*FF];
__device__ __align__(128) __nv_bfloat16 g_bhi[S*FF];
__device__ __align__(128) __nv_bfloat16 g_blo[S*FF];

// weight hi/lo, K-major transposed [N,K]
__device__ __align__(128) __nv_bfloat16 g_btv_hi[NLAYERS*H*H];
__device__ __align__(128) __nv_bfloat16 g_btv_lo[NLAYERS*H*H];
__device__ __align__(128) __nv_bfloat16 g_btp_hi[NLAYERS*H*H];
__device__ __align__(128) __nv_bfloat16 g_btp_lo[NLAYERS*H*H];
__device__ __align__(128) __nv_bfloat16 g_bt1_hi[NLAYERS*H*FF];
__device__ __align__(128) __nv_bfloat16 g_bt1_lo[NLAYERS*H*FF];
__device__ __align__(128) __nv_bfloat16 g_bt2_hi[NLAYERS*H*FF];
__device__ __align__(128) __nv_bfloat16 g_bt2_lo[NLAYERS*H*FF];
__device__ __align__(128) __half g_wlm_f16[VPAD*H];  // fp16 LM weights, pad rows stay zero
__device__ __align__(128) __half g_xf_f16[SZ_SH];    // fp16 final-LN activations

// ---------------- PTX helpers ----------------
__device__ __forceinline__ uint32_t smem_u32(const void* p) {
    uint32_t a;
    asm("{ .reg .u64 t; cvta.to.shared.u64 t, %1; cvt.u32.u64 %0, t; }" : "=r"(a) : "l"(p));
    return a;
}
__device__ __forceinline__ void cp16(uint32_t dst, const void* src) {
    asm volatile("cp.async.cg.shared.global [%0], [%1], 16;" :: "r"(dst), "l"(src));
}
__device__ __forceinline__ void cp_commit() { asm volatile("cp.async.commit_group;" ::: "memory"); }
template<int N> __device__ __forceinline__ void cp_wait() {
    asm volatile("cp.async.wait_group %0;" :: "n"(N) : "memory");
}
__device__ __forceinline__ void ldsm4(uint32_t& r0, uint32_t& r1, uint32_t& r2, uint32_t& r3,
                                      uint32_t addr) {
    asm volatile("ldmatrix.sync.aligned.m8n8.x4.shared.b16 {%0,%1,%2,%3}, [%4];"
                 : "=r"(r0), "=r"(r1), "=r"(r2), "=r"(r3) : "r"(addr));
}
__device__ __forceinline__ void mma16816(float& d0, float& d1, float& d2, float& d3,
                                         uint32_t a0, uint32_t a1, uint32_t a2, uint32_t a3,
                                         uint32_t b0, uint32_t b1) {
    asm volatile("mma.sync.aligned.m16n8k16.row.col.f32.bf16.bf16.f32 "
                 "{%0,%1,%2,%3}, {%4,%5,%6,%7}, {%8,%9}, {%0,%1,%2,%3};"
                 : "+f"(d0), "+f"(d1), "+f"(d2), "+f"(d3)
                 : "r"(a0), "r"(a1), "r"(a2), "r"(a3), "r"(b0), "r"(b1));
}
__device__ __forceinline__ void mma16816h(float& d0, float& d1, float& d2, float& d3,
                                          uint32_t a0, uint32_t a1, uint32_t a2, uint32_t a3,
                                          uint32_t b0, uint32_t b1) {
    asm volatile("mma.sync.aligned.m16n8k16.row.col.f32.f16.f16.f32 "
                 "{%0,%1,%2,%3}, {%4,%5,%6,%7}, {%8,%9}, {%0,%1,%2,%3};"
                 : "+f"(d0), "+f"(d1), "+f"(d2), "+f"(d3)
                 : "r"(a0), "r"(a1), "r"(a2), "r"(a3), "r"(b0), "r"(b1));
}

__device__ __forceinline__ float gelu_exact(float x) {
    return 0.5f * x * (1.0f + erff(x * 0.70710678118654752f));
}

// swizzled 64B-row offset: row r, 16B chunk c (0..3)
__device__ __forceinline__ uint32_t swz(uint32_t r, uint32_t c) {
    return r * 64 + ((c ^ ((r >> 1) & 3)) << 4);
}

// pack 4 floats into bf16 hi/lo pairs (8B each)
__device__ __forceinline__ void split4(float o0, float o1, float o2, float o3,
                                       uint2& hv, uint2& lv) {
    __nv_bfloat162 h01 = __floats2bfloat162_rn(o0, o1);
    __nv_bfloat162 h23 = __floats2bfloat162_rn(o2, o3);
    float e0 = o0 - __bfloat162float(h01.x), e1 = o1 - __bfloat162float(h01.y);
    float e2 = o2 - __bfloat162float(h23.x), e3 = o3 - __bfloat162float(h23.y);
    __nv_bfloat162 l01 = __floats2bfloat162_rn(e0, e1);
    __nv_bfloat162 l23 = __floats2bfloat162_rn(e2, e3);
    hv = make_uint2(*(uint32_t*)&h01, *(uint32_t*)&h23);
    lv = make_uint2(*(uint32_t*)&l01, *(uint32_t*)&l23);
}

// ---------------- TM64 HMMA GEMM (bf16x3): CTA 64x128, BK=32, 4-stage ----------------
// 8 warps (2x4) of 32x32 tiles. MODE 0: fp32 + bias. MODE 1: gelu + bf16 hi/lo.
#define S64_AHI 0
#define S64_ALO 4096
#define S64_BHI 8192
#define S64_BLO 16384
#define STAGE64 24576
#define GEMM64_SMEM (4*STAGE64)

template<int MODE>
__global__ __launch_bounds__(256, 2)
void gemm_hmma64(const __nv_bfloat16* __restrict__ Ahi, const __nv_bfloat16* __restrict__ Alo,
                 const __nv_bfloat16* __restrict__ Bhi, const __nv_bfloat16* __restrict__ Blo,
                 const float* __restrict__ bias, float* __restrict__ C,
                 __nv_bfloat16* __restrict__ Chi, __nv_bfloat16* __restrict__ Clo,
                 int N, int K) {
    extern __shared__ char smem[];
    const uint32_t sb = smem_u32(smem);
    const int tid  = threadIdx.x;
    const int wid  = tid >> 5;
    const int lane = tid & 31;
    const int wrow = wid & 1;
    const int wcol = wid >> 1;
    const int bm = blockIdx.y << 6;
    const long bn = (long)blockIdx.x << 7;
    const int nc = K >> 5;

    const uint32_t rt = tid >> 2, ct = tid & 3;
    const uint32_t soA  = swz(rt, ct);
    const uint32_t soB1 = swz(rt + 64, ct);

    #define LOAD_FULL(kc, s) do {                                                      \
        uint32_t st_ = sb + (s) * STAGE64;                                              \
        size_t ga  = ((size_t)(bm + rt) * K + (kc) * 32 + ct * 8) * 2;                  \
        size_t gb0 = ((size_t)(bn + rt) * K + (kc) * 32 + ct * 8) * 2;                  \
        size_t gb1 = ((size_t)(bn + rt + 64) * K + (kc) * 32 + ct * 8) * 2;             \
        cp16(st_ + S64_AHI + soA,  (const char*)Ahi + ga);                              \
        cp16(st_ + S64_ALO + soA,  (const char*)Alo + ga);                              \
        cp16(st_ + S64_BHI + soA,  (const char*)Bhi + gb0);                             \
        cp16(st_ + S64_BLO + soA,  (const char*)Blo + gb0);                             \
        cp16(st_ + S64_BHI + soB1, (const char*)Bhi + gb1);                             \
        cp16(st_ + S64_BLO + soB1, (const char*)Blo + gb1);                             \
    } while (0)

    const int lane8 = lane & 7, sub = lane >> 3;
    const uint32_t ra = wrow * 32 + (sub & 1) * 8 + lane8;
    const uint32_t aks0 = swz(ra, (sub >> 1));
    const uint32_t aks1 = swz(ra, (sub >> 1) + 2);
    const uint32_t rb = wcol * 32 + lane8;
    const uint32_t boffs = swz(rb, sub);

    float acc[2][4][4];
    #pragma unroll
    for (int i = 0; i < 2; i++)
        #pragma unroll
        for (int j = 0; j < 4; j++)
            #pragma unroll
            for (int e = 0; e < 4; e++) acc[i][j][e] = 0.f;

    int slot = 0;
    LOAD_FULL(0, 0); cp_commit();
    LOAD_FULL(1, 1); cp_commit();
    LOAD_FULL(2, 2); cp_commit();
    for (int it = 0; it < nc; it++) {
        cp_wait<2>();
        __syncthreads();
        if (it + 3 < nc) {
            int ns = slot + 3; if (ns >= 4) ns -= 4;
            LOAD_FULL(it + 3, ns);
        }
        cp_commit();
        const uint32_t st = sb + slot * STAGE64;

        uint32_t bh[4][4], bl[4][4], ah[2][2][4], al[2][2][4];
        #pragma unroll
        for (int nj = 0; nj < 4; nj++) {
            ldsm4(bh[nj][0], bh[nj][1], bh[nj][2], bh[nj][3], st + S64_BHI + boffs + nj * 512);
            ldsm4(bl[nj][0], bl[nj][1], bl[nj][2], bl[nj][3], st + S64_BLO + boffs + nj * 512);
        }
        #pragma unroll
        for (int mi = 0; mi < 2; mi++) {
            ldsm4(ah[0][mi][0], ah[0][mi][1], ah[0][mi][2], ah[0][mi][3],
                  st + S64_AHI + aks0 + mi * 1024);
            ldsm4(ah[1][mi][0], ah[1][mi][1], ah[1][mi][2], ah[1][mi][3],
                  st + S64_AHI + aks1 + mi * 1024);
            ldsm4(al[0][mi][0], al[0][mi][1], al[0][mi][2], al[0][mi][3],
                  st + S64_ALO + aks0 + mi * 1024);
            ldsm4(al[1][mi][0], al[1][mi][1], al[1][mi][2], al[1][mi][3],
                  st + S64_ALO + aks1 + mi * 1024);
        }
        #pragma unroll
        for (int ks = 0; ks < 2; ks++) {
            #pragma unroll
            for (int mi = 0; mi < 2; mi++)
                #pragma unroll
                for (int nj = 0; nj < 4; nj++)
                    mma16816(acc[mi][nj][0], acc[mi][nj][1], acc[mi][nj][2], acc[mi][nj][3],
                             ah[ks][mi][0], ah[ks][mi][1], ah[ks][mi][2], ah[ks][mi][3],
                             bh[nj][ks * 2], bh[nj][ks * 2 + 1]);
            #pragma unroll
            for (int mi = 0; mi < 2; mi++)
                #pragma unroll
                for (int nj = 0; nj < 4; nj++)
                    mma16816(acc[mi][nj][0], acc[mi][nj][1], acc[mi][nj][2], acc[mi][nj][3],
                             ah[ks][mi][0], ah[ks][mi][1], ah[ks][mi][2], ah[ks][mi][3],
                             bl[nj][ks * 2], bl[nj][ks * 2 + 1]);
            #pragma unroll
            for (int mi = 0; mi < 2; mi++)
                #pragma unroll
                for (int nj = 0; nj < 4; nj++)
                    mma16816(acc[mi][nj][0], acc[mi][nj][1], acc[mi][nj][2], acc[mi][nj][3],
                             al[ks][mi][0], al[ks][mi][1], al[ks][mi][2], al[ks][mi][3],
                             bh[nj][ks * 2], bh[nj][ks * 2 + 1]);
        }
        if (++slot == 4) slot = 0;
    }

    const int gr = lane >> 2;
    const int gc = (lane & 3) * 2;
    #pragma unroll
    for (int mi = 0; mi < 2; mi++) {
        size_t row0 = (size_t)(bm + wrow * 32 + mi * 16 + gr) * N;
        size_t row1 = row0 + (size_t)8 * N;
        #pragma unroll
        for (int nj = 0; nj < 4; nj++) {
            long c = bn + wcol * 32 + nj * 8 + gc;
            float b0 = bias[c], b1 = bias[c + 1];
            if (MODE == 0) {
                C[row0 + c]     = acc[mi][nj][0] + b0;
                C[row0 + c + 1] = acc[mi][nj][1] + b1;
                C[row1 + c]     = acc[mi][nj][2] + b0;
                C[row1 + c + 1] = acc[mi][nj][3] + b1;
            } else {
                float v0 = gelu_exact(acc[mi][nj][0] + b0);
                float v1 = gelu_exact(acc[mi][nj][1] + b1);
                float v2 = gelu_exact(acc[mi][nj][2] + b0);
                float v3 = gelu_exact(acc[mi][nj][3] + b1);
                __nv_bfloat162 hp0 = __floats2bfloat162_rn(v0, v1);
                __nv_bfloat162 hp1 = __floats2bfloat162_rn(v2, v3);
                float e0 = v0 - __bfloat162float(hp0.x), e1 = v1 - __bfloat162float(hp0.y);
                float e2 = v2 - __bfloat162float(hp1.x), e3 = v3 - __bfloat162float(hp1.y);
                __nv_bfloat162 lp0 = __floats2bfloat162_rn(e0, e1);
                __nv_bfloat162 lp1 = __floats2bfloat162_rn(e2, e3);
                *(uint32_t*)(Chi + row0 + c) = *(uint32_t*)&hp0;
                *(uint32_t*)(Clo + row0 + c) = *(uint32_t*)&lp0;
                *(uint32_t*)(Chi + row1 + c) = *(uint32_t*)&hp1;
                *(uint32_t*)(Clo + row1 + c) = *(uint32_t*)&lp1;
            }
        }
    }
    #undef LOAD_FULL
}

// ---------------- fp16 single-term GEMM (LM head), 4-stage ----------------
#define F_TA 0
#define F_TB 8192
#define F_STAGE 16384
#define F16_SMEM (4*F_STAGE)

__global__ __launch_bounds__(256, 2)
void gemm_f16(const __half* __restrict__ A, const __half* __restrict__ B,
              const float* __restrict__ bias, float* __restrict__ C, int N, int K) {
    extern __shared__ char smem[];
    const uint32_t sb = smem_u32(smem);
    const int tid  = threadIdx.x;
    const int wid  = tid >> 5;
    const int lane = tid & 31;
    const int wrow = wid & 1;
    const int wcol = wid >> 1;
    const int bm = blockIdx.x << 7;
    const long bn = (long)blockIdx.y << 7;
    const int nc = K >> 5;

    const uint32_t r0t = tid >> 2, c0t = tid & 3;
    const uint32_t r1t = r0t + 64;
    const uint32_t so0 = swz(r0t, c0t);
    const uint32_t so1 = swz(r1t, c0t);

    #define LOAD_STAGE_F(kc, s) do {                                                   \
        uint32_t st_ = sb + (s) * F_STAGE;                                              \
        {                                                                               \
            size_t ga = ((size_t)(bm + r0t) * K + (kc) * 32 + c0t * 8) * 2;             \
            size_t gb = ((size_t)(bn + r0t) * K + (kc) * 32 + c0t * 8) * 2;             \
            cp16(st_ + F_TA + so0, (const char*)A + ga);                                \
            cp16(st_ + F_TB + so0, (const char*)B + gb);                                \
        }                                                                               \
        {                                                                               \
            size_t ga = ((size_t)(bm + r1t) * K + (kc) * 32 + c0t * 8) * 2;             \
            size_t gb = ((size_t)(bn + r1t) * K + (kc) * 32 + c0t * 8) * 2;             \
            cp16(st_ + F_TA + so1, (const char*)A + ga);                                \
            cp16(st_ + F_TB + so1, (const char*)B + gb);                                \
        }                                                                               \
    } while (0)

    LOAD_STAGE_F(0, 0); cp_commit();
    LOAD_STAGE_F(1, 1); cp_commit();
    LOAD_STAGE_F(2, 2); cp_commit();

    const int lane8 = lane & 7, sub = lane >> 3;
    const uint32_t ra = wrow * 64 + (sub & 1) * 8 + lane8;
    const uint32_t aks0 = swz(ra, (sub >> 1));
    const uint32_t aks1 = swz(ra, (sub >> 1) + 2);
    const uint32_t rb = wcol * 32 + lane8;
    const uint32_t boffs = swz(rb, sub);

    float acc[4][4][4];
    #pragma unroll
    for (int i = 0; i < 4; i++)
        #pragma unroll
        for (int j = 0; j < 4; j++)
            #pragma unroll
            for (int e = 0; e < 4; e++) acc[i][j][e] = 0.f;

    int slot = 0;
    for (int it = 0; it < nc; it++) {
        cp_wait<2>();
        __syncthreads();
        if (it + 3 < nc) {
            int ns = slot + 3; if (ns >= 4) ns -= 4;
            LOAD_STAGE_F(it + 3, ns);
        }
        cp_commit();
        const uint32_t st = sb + slot * F_STAGE;

        uint32_t bf[4][4];
        #pragma unroll
        for (int nj = 0; nj < 4; nj++)
            ldsm4(bf[nj][0], bf[nj][1], bf[nj][2], bf[nj][3], st + F_TB + boffs + nj * 512);
        #pragma unroll
        for (int ks = 0; ks < 2; ks++) {
            const uint32_t ao = (ks == 0) ? aks0 : aks1;
            uint32_t a[4][4];
            #pragma unroll
            for (int mi = 0; mi < 4; mi++)
                ldsm4(a[mi][0], a[mi][1], a[mi][2], a[mi][3], st + F_TA + ao + mi * 1024);
            #pragma unroll
            for (int mi = 0; mi < 4; mi++)
                #pragma unroll
                for (int nj = 0; nj < 4; nj++)
                    mma16816h(acc[mi][nj][0], acc[mi][nj][1], acc[mi][nj][2], acc[mi][nj][3],
                              a[mi][0], a[mi][1], a[mi][2], a[mi][3],
                              bf[nj][ks * 2], bf[nj][ks * 2 + 1]);
        }
        if (++slot == 4) slot = 0;
    }

    const int gr = lane >> 2;
    const int gc = (lane & 3) * 2;
    #pragma unroll
    for (int mi = 0; mi < 4; mi++) {
        size_t row0 = (size_t)(bm + wrow * 64 + mi * 16 + gr) * N;
        size_t row1 = row0 + (size_t)8 * N;
        #pragma unroll
        for (int nj = 0; nj < 4; nj++) {
            long c = bn + wcol * 32 + nj * 8 + gc;
            if (c < N) {
                C[row0 + c] = acc[mi][nj][0] + bias[c];
                C[row1 + c] = acc[mi][nj][2] + bias[c];
            }
            if (c + 1 < N) {
                C[row0 + c + 1] = acc[mi][nj][1] + bias[c + 1];
                C[row1 + c + 1] = acc[mi][nj][3] + bias[c + 1];
            }
        }
    }
    #undef LOAD_STAGE_F
}

// ---------------- weight transpose + split (bf16 hi/lo), 16B stores ----------------
// QKV==2: V-only per-(layer,head): ob = layer*H*H + head*64*H
template<int QKV>
__global__ __launch_bounds__(256)
void transpose_split(const float* __restrict__ src0,
                     __nv_bfloat16* __restrict__ hi, __nv_bfloat16* __restrict__ lo,
                     int R, int C) {
    __shared__ float t[128][33];
    int z = blockIdx.z;
    const float* src = src0;
    const size_t ib = (size_t)z * R * C;
    size_t ob;
    if (QKV == 2) ob = (size_t)(z >> 4) * (H * H) + (size_t)(z & 15) * (64 * H);
    else          ob = ib;
    const int r0 = blockIdx.y * 128, c0 = blockIdx.x * 32;
    const int cc = threadIdx.x & 31, rb = threadIdx.x >> 5;
    const bool cok = (c0 + cc) < C;
    #pragma unroll
    for (int p = 0; p < 16; p++) {
        int rr = rb + p * 8;
        t[rr][cc] = cok ? src[ib + (size_t)(r0 + rr) * C + c0 + cc] : 0.f;
    }
    __syncthreads();
    const int oc2 = threadIdx.x >> 4;
    const int r8  = (threadIdx.x & 15) * 8;
    #pragma unroll
    for (int cp = 0; cp < 2; cp++) {
        int col = cp * 16 + oc2;
        if (c0 + col < C) {
            uint32_t hw[4], lw[4];
            #pragma unroll
            for (int i = 0; i < 4; i++) {
                float f0 = t[r8 + 2 * i][col], f1 = t[r8 + 2 * i + 1][col];
                __nv_bfloat162 hp = __floats2bfloat162_rn(f0, f1);
                hw[i] = *(uint32_t*)&hp;
                float e0 = f0 - __bfloat162float(hp.x);
                float e1 = f1 - __bfloat162float(hp.y);
                __nv_bfloat162 lp = __floats2bfloat162_rn(e0, e1);
                lw[i] = *(uint32_t*)&lp;
            }
            size_t obase = ob + (size_t)(c0 + col) * R + r0 + r8;
            *(uint4*)(hi + obase) = make_uint4(hw[0], hw[1], hw[2], hw[3]);
            *(uint4*)(lo + obase) = make_uint4(lw[0], lw[1], lw[2], lw[3]);
        }
    }
}

// ---------------- fp16 weight transpose (LM head), 16B stores ----------------
__global__ __launch_bounds__(256)
void transpose_f16(const float* __restrict__ src, __half* __restrict__ out, int R, int C) {
    __shared__ float t[128][33];
    const int r0 = blockIdx.y * 128, c0 = blockIdx.x * 32;
    const int cc = threadIdx.x & 31, rb = threadIdx.x >> 5;
    const bool cok = (c0 + cc) < C;
    #pragma unroll
    for (int p = 0; p < 16; p++) {
        int rr = rb + p * 8;
        t[rr][cc] = cok ? src[(size_t)(r0 + rr) * C + c0 + cc] : 0.f;
    }
    __syncthreads();
    const int oc2 = threadIdx.x >> 4;
    const int r8  = (threadIdx.x & 15) * 8;
    #pragma unroll
    for (int cp = 0; cp < 2; cp++) {
        int col = cp * 16 + oc2;
        if (c0 + col < C) {
            uint32_t hw[4];
            #pragma unroll
            for (int i = 0; i < 4; i++) {
                __half2 hp = __floats2half2_rn(t[r8 + 2 * i][col], t[r8 + 2 * i + 1][col]);
                hw[i] = *(uint32_t*)&hp;
            }
            size_t obase = (size_t)(c0 + col) * R + r0 + r8;
            *(uint4*)(out + obase) = make_uint4(hw[0], hw[1], hw[2], hw[3]);
        }
    }
}

// ---------------- embedding: x = emb[tok] + pos, + split ----------------
__global__ void embed_kernel(const int* __restrict__ tok, const float* __restrict__ emb,
                             const float* __restrict__ pos, float* __restrict__ x,
                             __nv_bfloat16* __restrict__ hi, __nv_bfloat16* __restrict__ lo) {
    int i4 = blockIdx.x * 256 + threadIdx.x;
    int e = i4 * 4;
    int s = e >> 10, h = e & 1023;
    float4 ev = *(const float4*)(emb + (size_t)tok[s] * H + h);
    float4 pv = *(const float4*)(pos + e);
    float o0 = ev.x + pv.x, o1 = ev.y + pv.y, o2 = ev.z + pv.z, o3 = ev.w + pv.w;
    *(float4*)(x + e) = make_float4(o0, o1, o2, o3);
    uint2 hv, lv;
    split4(o0, o1, o2, o3, hv, lv);
    *(uint2*)(hi + e) = hv;
    *(uint2*)(lo + e) = lv;
}

// ---------------- qwk: q_last = x[S-1]·Wq[head];  w~ = Wk[head]·q_last ----------------
__global__ __launch_bounds__(256)
void qwk_kernel(const float* __restrict__ x, const float* __restrict__ Wq,
                const float* __restrict__ Wk, float* __restrict__ wt) {
    __shared__ float qs[64];
    __shared__ float red[256];
    const int h = blockIdx.x, tid = threadIdx.x;
    const float* xr = x + (size_t)(S - 1) * H;
    const int d = tid & 63, qr = tid >> 6;
    const float* wq = Wq + (size_t)h * H * DH;
    float acc = 0.f;
    for (int j = qr * 256; j < qr * 256 + 256; j++)
        acc = fmaf(xr[j], wq[(size_t)j * DH + d], acc);
    red[tid] = acc; __syncthreads();
    if (tid < 64) qs[tid] = red[tid] + red[tid + 64] + red[tid + 128] + red[tid + 192];
    __syncthreads();
    const float* wk = Wk + (size_t)h * H * DH;
    for (int j = tid; j < H; j += 256) {
        float a = 0.f;
        #pragma unroll
        for (int d2 = 0; d2 < 64; d2++) a = fmaf(wk[(size_t)j * DH + d2], qs[d2], a);
        wt[h * H + j] = a;
    }
}

// ---------------- sv: s[t,h] = x[t]·w~[h];  part[seg,col] = sum_64 v ----------------
__global__ __launch_bounds__(256)
void sv_kernel(const float* __restrict__ x, const float* __restrict__ v,
               const float* __restrict__ wt, float* __restrict__ s,
               float* __restrict__ part) {
    const int seg = blockIdx.x, tid = threadIdx.x, s0 = seg * 64;
    #pragma unroll
    for (int k = 0; k < 4; k++) {
        int oi = tid + k * 256;
        int t = s0 + (oi >> 4), h = oi & 15;
        const float* xr = x + (size_t)t * H;
        const float* w = wt + h * H;
        float a0 = 0.f, a1 = 0.f, a2 = 0.f, a3 = 0.f;
        for (int j = 0; j < H; j += 4) {
            a0 = fmaf(xr[j],     w[j],     a0);
            a1 = fmaf(xr[j + 1], w[j + 1], a1);
            a2 = fmaf(xr[j + 2], w[j + 2], a2);
            a3 = fmaf(xr[j + 3], w[j + 3], a3);
        }
        s[(size_t)t * NH + h] = (a0 + a1) + (a2 + a3);
    }
    #pragma unroll
    for (int k = 0; k < 4; k++) {
        int col = tid + k * 256;
        float a = 0.f;
        for (int r = 0; r < 64; r++) a += v[(size_t)(s0 + r) * H + col];
        part[seg * 1024 + col] = a;
    }
}

// ---------------- alast[h,d] = 0.125 * sum_t s[t,h]·v[t, h*64+d] ----------------
__global__ __launch_bounds__(256)
void alast_kernel(const float* __restrict__ s, const float* __restrict__ v,
                  float* __restrict__ alast) {
    __shared__ float red[256];
    const int h = blockIdx.x, tid = threadIdx.x;
    const int d = tid & 63, p = tid >> 6;
    float a0 = 0.f, a1 = 0.f;
    for (int t = p * 512; t < p * 512 + 512; t += 2) {
        a0 = fmaf(s[(size_t)t * NH + h],       v[(size_t)t * H + h * 64 + d],       a0);
        a1 = fmaf(s[(size_t)(t + 1) * NH + h], v[(size_t)(t + 1) * H + h * 64 + d], a1);
    }
    red[tid] = a0 + a1; __syncthreads();
    if (tid < 64)
        alast[h * 64 + tid] = 0.125f * (red[tid] + red[tid + 64] + red[tid + 128] + red[tid + 192]);
}

// ---------------- attn: att = -1e9*suffix(V); row S-1 = alast; emit hi/lo ----------------
__global__ __launch_bounds__(256)
void attn_sfx(const float* __restrict__ v, const float* __restrict__ part,
              const float* __restrict__ alast,
              __nv_bfloat16* __restrict__ ahi, __nv_bfloat16* __restrict__ alo) {
    __shared__ float Vs[64][65];
    __shared__ float red[4][64];
    const int head = blockIdx.y;
    const int bidx = blockIdx.x;
    const int s0 = bidx * 64;
    const int tid = threadIdx.x;
    for (int i = tid; i < 4096; i += 256) {
        int r = i >> 6, c = i & 63;
        Vs[r][c] = v[(size_t)(s0 + r) * H + head * DH + c];
    }
    __syncthreads();
    const int vc = tid & 63, q = tid >> 6;
    {
        float qs = 0.f;
        #pragma unroll
        for (int r = 0; r < 16; r++) qs += Vs[q * 16 + r][vc];
        red[q][vc] = qs;
    }
    __syncthreads();
    {
        float run = 0.f;
        for (int b2 = bidx + 1; b2 < 32; b2++)
            run += part[(size_t)b2 * 1024 + head * DH + vc];
        for (int q2 = q + 1; q2 < 4; q2++) run += red[q2][vc];
        for (int r = q * 16 + 15; r >= q * 16; r--) {
            float tmpv = Vs[r][vc];
            Vs[r][vc] = run;
            run += tmpv;
        }
    }
    __syncthreads();
    #pragma unroll
    for (int k = 0; k < 4; k++) {
        int i = tid + k * 256;
        int r = i >> 4, c4 = (i & 15) * 4;
        float o0, o1, o2, o3;
        if (bidx == 31 && r == 63) {
            o0 = alast[head * 64 + c4];     o1 = alast[head * 64 + c4 + 1];
            o2 = alast[head * 64 + c4 + 2]; o3 = alast[head * 64 + c4 + 3];
        } else {
            o0 = -1e9f * Vs[r][c4];     o1 = -1e9f * Vs[r][c4 + 1];
            o2 = -1e9f * Vs[r][c4 + 2]; o3 = -1e9f * Vs[r][c4 + 3];
        }
        size_t sb = (size_t)(s0 + r) * H + head * DH + c4;
        uint2 hv, lv;
        split4(o0, o1, o2, o3, hv, lv);
        *(uint2*)(ahi + sb) = hv;
        *(uint2*)(alo + sb) = lv;
    }
}

// ---------------- LayerNorm (+residual) + fused split, warp-shuffle reduce ----------------
template<bool ADD, bool WF32, int OUTK>
__global__ __launch_bounds__(256)
void ln_kernel(const float* __restrict__ t, const float* __restrict__ xin,
               const float* __restrict__ g, const float* __restrict__ b,
               float* __restrict__ outf,
               __nv_bfloat16* __restrict__ hi, __nv_bfloat16* __restrict__ lo,
               __half* __restrict__ outh) {
    const int row = blockIdx.x;
    const int tid = threadIdx.x;
    const int wid = tid >> 5, lane = tid & 31;
    float4 v = *(const float4*)(t + (size_t)row * H + tid * 4);
    __shared__ float wred[8];
    __shared__ float stat[2];

    float s = v.x + v.y + v.z + v.w;
    #pragma unroll
    for (int o = 16; o > 0; o >>= 1) s += __shfl_xor_sync(0xFFFFFFFFu, s, o);
    if (lane == 0) wred[wid] = s;
    __syncthreads();
    if (tid == 0) {
        float tot = 0.f;
        #pragma unroll
        for (int w = 0; w < 8; w++) tot += wred[w];
        stat[0] = tot * (1.0f / H);
    }
    __syncthreads();
    float mean = stat[0];

    float dx = v.x - mean, dy = v.y - mean, dz = v.z - mean, dw = v.w - mean;
    float vs = dx * dx + dy * dy + dz * dz + dw * dw;
    #pragma unroll
    for (int o = 16; o > 0; o >>= 1) vs += __shfl_xor_sync(0xFFFFFFFFu, vs, o);
    if (lane == 0) wred[wid] = vs;
    __syncthreads();
    if (tid == 0) {
        float tot = 0.f;
        #pragma unroll
        for (int w = 0; w < 8; w++) tot += wred[w];
        stat[1] = rsqrtf(tot * (1.0f / H) + 1e-5f);
    }
    __syncthreads();
    float rstd = stat[1];

    int h = tid * 4;
    float4 gv = *(const float4*)(g + h);
    float4 bv = *(const float4*)(b + h);
    float o0 = dx * rstd * gv.x + bv.x;
    float o1 = dy * rstd * gv.y + bv.y;
    float o2 = dz * rstd * gv.z + bv.z;
    float o3 = dw * rstd * gv.w + bv.w;
    if (ADD) {
        float4 xv = *(const float4*)(xin + (size_t)row * H + h);
        o0 += xv.x; o1 += xv.y; o2 += xv.z; o3 += xv.w;
    }
    if (WF32) *(float4*)(outf + (size_t)row * H + h) = make_float4(o0, o1, o2, o3);
    if (OUTK == 0) {
        uint2 hv, lv;
        split4(o0, o1, o2, o3, hv, lv);
        *(uint2*)(hi + (size_t)row * H + h) = hv;
        *(uint2*)(lo + (size_t)row * H + h) = lv;
    } else {
        __half2 h0 = __floats2half2_rn(o0, o1);
        __half2 h1 = __floats2half2_rn(o2, o3);
        *(uint2*)(outh + (size_t)row * H + h) = make_uint2(*(uint32_t*)&h0, *(uint32_t*)&h1);
    }
}

// ---------------- launch ----------------
extern "C" void kernel_launch(void* const* d_in, const int* in_sizes, int n_in,
                              void* d_out, int out_size) {
    const int*   tokens = (const int*)  d_in[0];
    const float* emb    = (const float*)d_in[1];
    const float* pos    = (const float*)d_in[2];
    const float* Wq     = (const float*)d_in[3];
    const float* Wk     = (const float*)d_in[4];
    const float* Wv     = (const float*)d_in[5];
    const float* Wp     = (const float*)d_in[6];
    const float* bp     = (const float*)d_in[7];
    const float* W1     = (const float*)d_in[8];
    const float* b1     = (const float*)d_in[9];
    const float* W2     = (const float*)d_in[10];
    const float* b2     = (const float*)d_in[11];
    const float* ln_g   = (const float*)d_in[12];
    const float* ln_b   = (const float*)d_in[13];
    const float* Wlm    = (const float*)d_in[14];
    const float* blm    = (const float*)d_in[15];
    float* out = (float*)d_out;
    const int Vv = in_sizes[15];

    float *x, *tmp, *res, *v, *part, *sbuf, *wt, *al, *zb;
    __nv_bfloat16 *ahi, *alo, *bhi, *blo;
    __nv_bfloat16 *btv_hi, *btv_lo, *btp_hi, *btp_lo;
    __nv_bfloat16 *bt1_hi, *bt1_lo, *bt2_hi, *bt2_lo;
    __half *wlm, *xf16;
    cudaGetSymbolAddress((void**)&x, g_x);       cudaGetSymbolAddress((void**)&tmp, g_tmp);
    cudaGetSymbolAddress((void**)&res, g_res);   cudaGetSymbolAddress((void**)&v, g_v);
    cudaGetSymbolAddress((void**)&part, g_part); cudaGetSymbolAddress((void**)&sbuf, g_s);
    cudaGetSymbolAddress((void**)&wt, g_wt);     cudaGetSymbolAddress((void**)&al, g_alast);
    cudaGetSymbolAddress((void**)&zb, g_zb);
    cudaGetSymbolAddress((void**)&ahi, g_ahi);   cudaGetSymbolAddress((void**)&alo, g_alo);
    cudaGetSymbolAddress((void**)&bhi, g_bhi);   cudaGetSymbolAddress((void**)&blo, g_blo);
    cudaGetSymbolAddress((void**)&btv_hi, g_btv_hi); cudaGetSymbolAddress((void**)&btv_lo, g_btv_lo);
    cudaGetSymbolAddress((void**)&btp_hi, g_btp_hi); cudaGetSymbolAddress((void**)&btp_lo, g_btp_lo);
    cudaGetSymbolAddress((void**)&bt1_hi, g_bt1_hi); cudaGetSymbolAddress((void**)&bt1_lo, g_bt1_lo);
    cudaGetSymbolAddress((void**)&bt2_hi, g_bt2_hi); cudaGetSymbolAddress((void**)&bt2_lo, g_bt2_lo);
    cudaGetSymbolAddress((void**)&wlm, g_wlm_f16);   cudaGetSymbolAddress((void**)&xf16, g_xf_f16);

    cudaFuncSetAttribute(gemm_hmma64<0>, cudaFuncAttributeMaxDynamicSharedMemorySize, GEMM64_SMEM);
    cudaFuncSetAttribute(gemm_hmma64<1>, cudaFuncAttributeMaxDynamicSharedMemorySize, GEMM64_SMEM);
    cudaFuncSetAttribute(gemm_f16, cudaFuncAttributeMaxDynamicSharedMemorySize, F16_SMEM);

    dim3 tb(256);
    // idx0: embed
    embed_kernel<<<(S * H) / 1024, 256>>>(tokens, emb, pos, x, ahi, alo);
    // idx1: V weight transpose only (Q/K weights are consumed raw in qwk_kernel)
    transpose_split<2><<<dim3(2, 8, NLAYERS * NH), tb>>>(Wv, btv_hi, btv_lo, H, DH);
    // idx2: proj weights
    transpose_split<0><<<dim3(32, 8, NLAYERS), tb>>>(Wp, btp_hi, btp_lo, H, H);
    // idx3: V GEMM layer 0 (profile target)
    gemm_hmma64<0><<<dim3(8, 32), 256, GEMM64_SMEM>>>(ahi, alo, btv_hi, btv_lo,
                                                      zb, v, nullptr, nullptr, H, H);
    // remaining weight transposes
    transpose_split<0><<<dim3(128, 8, NLAYERS), tb>>>(W1, bt1_hi, bt1_lo, H, FF);
    transpose_split<0><<<dim3(32, 32, NLAYERS), tb>>>(W2, bt2_hi, bt2_lo, FF, H);
    transpose_f16<<<dim3((Vv + 31) / 32, 8), tb>>>(Wlm, wlm, H, Vv);

    for (int l = 0; l < NLAYERS; l++) {
        size_t oV = (size_t)l * H * H;
        size_t oH = (size_t)l * H * H;
        size_t oF = (size_t)l * H * FF;
        size_t oW = (size_t)l * NH * H * DH;

        if (l > 0)
            gemm_hmma64<0><<<dim3(8, 32), 256, GEMM64_SMEM>>>(ahi, alo, btv_hi + oV, btv_lo + oV,
                                                              zb, v, nullptr, nullptr, H, H);
        qwk_kernel<<<NH, 256>>>(x, Wq + oW, Wk + oW, wt);
        sv_kernel<<<32, 256>>>(x, v, wt, sbuf, part);
        alast_kernel<<<NH, 256>>>(sbuf, v, al);
        attn_sfx<<<dim3(32, NH), 256>>>(v, part, al, ahi, alo);

        gemm_hmma64<0><<<dim3(8, 32), 256, GEMM64_SMEM>>>(ahi, alo, btp_hi + oH, btp_lo + oH,
                                                          bp + (size_t)l * H, tmp, nullptr, nullptr,
                                                          H, H);
        ln_kernel<true, true, 0><<<S, 256>>>(tmp, x, ln_g, ln_b, res, ahi, alo, nullptr);

        gemm_hmma64<1><<<dim3(32, 32), 256, GEMM64_SMEM>>>(ahi, alo, bt1_hi + oF, bt1_lo + oF,
                                                           b1 + (size_t)l * FF, nullptr, bhi, blo,
                                                           FF, H);
        gemm_hmma64<0><<<dim3(8, 32), 256, GEMM64_SMEM>>>(bhi, blo, bt2_hi + oF, bt2_lo + oF,
                                                          b2 + (size_t)l * H, tmp, nullptr, nullptr,
                                                          H, FF);
        ln_kernel<true, true, 0><<<S, 256>>>(tmp, res, ln_g, ln_b, x, ahi, alo, nullptr);
    }

    // final LN -> fp16, LM head in fp16 HMMA
    ln_kernel<false, false, 1><<<S, 256>>>(x, nullptr, ln_g, ln_b, nullptr, nullptr, nullptr, xf16);
    gemm_f16<<<dim3(16, VPAD / 128), 256, F16_SMEM>>>(xf16, wlm, blm, out, Vv, H);
}

// round 17
// speedup vs baseline: 1.4670x; 1.4670x over previous
#include <cuda_runtime.h>
#include <cuda_bf16.h>
#include <cuda_fp16.h>
#include <math.h>
#include <stdint.h>

#define S  2048
#define H  1024
#define NH 16
#define DH 64
#define FF 4096
#define NLAYERS 6
#define VPAD 50432     // 50257 padded to multiple of 128

#define SZ_SH (S*H)

// ---------------- device scratch ----------------
__device__ __align__(16) float g_x[SZ_SH];
__device__ __align__(16) float g_tmp[SZ_SH];
__device__ __align__(16) float g_res[SZ_SH];
__device__ __align__(16) float g_v[SZ_SH];
__device__ __align__(16) float g_part[32*1024];     // V column sums per 64-row block
__device__ __align__(16) float g_s[S*NH];           // s[t,h] scores for last row
__device__ __align__(16) float g_wt[NH*H];          // w~ = Wk @ q_last per head
__device__ __align__(16) float g_alast[NH*DH];      // attn row S-1 (scaled)
__device__ __align__(16) float g_zb[8192];          // zero bias (never written)

// activation hi/lo
__device__ __align__(128) __nv_bfloat16 g_ahi[S*FF];
__device__ __align__(128) __nv_bfloat16 g_alo[S*FF];
__device__ __align__(128) __nv_bfloat16 g_bhi[S*FF];
__device__ __align__(128) __nv_bfloat16 g_blo[S*FF];

// weight hi/lo, K-major transposed [N,K]
__device__ __align__(128) __nv_bfloat16 g_btv_hi[NLAYERS*H*H];
__device__ __align__(128) __nv_bfloat16 g_btv_lo[NLAYERS*H*H];
__device__ __align__(128) __nv_bfloat16 g_btp_hi[NLAYERS*H*H];
__device__ __align__(128) __nv_bfloat16 g_btp_lo[NLAYERS*H*H];
__device__ __align__(128) __nv_bfloat16 g_bt1_hi[NLAYERS*H*FF];
__device__ __align__(128) __nv_bfloat16 g_bt1_lo[NLAYERS*H*FF];
__device__ __align__(128) __nv_bfloat16 g_bt2_hi[NLAYERS*H*FF];
__device__ __align__(128) __nv_bfloat16 g_bt2_lo[NLAYERS*H*FF];
__device__ __align__(128) __half g_wlm_f16[VPAD*H];  // fp16 LM weights, pad rows stay zero
__device__ __align__(128) __half g_xf_f16[SZ_SH];    // fp16 final-LN activations

// ---------------- PTX helpers ----------------
__device__ __forceinline__ uint32_t smem_u32(const void* p) {
    uint32_t a;
    asm("{ .reg .u64 t; cvta.to.shared.u64 t, %1; cvt.u32.u64 %0, t; }" : "=r"(a) : "l"(p));
    return a;
}
__device__ __forceinline__ void cp16(uint32_t dst, const void* src) {
    asm volatile("cp.async.cg.shared.global [%0], [%1], 16;" :: "r"(dst), "l"(src));
}
__device__ __forceinline__ void cp_commit() { asm volatile("cp.async.commit_group;" ::: "memory"); }
template<int N> __device__ __forceinline__ void cp_wait() {
    asm volatile("cp.async.wait_group %0;" :: "n"(N) : "memory");
}
__device__ __forceinline__ void ldsm4(uint32_t& r0, uint32_t& r1, uint32_t& r2, uint32_t& r3,
                                      uint32_t addr) {
    asm volatile("ldmatrix.sync.aligned.m8n8.x4.shared.b16 {%0,%1,%2,%3}, [%4];"
                 : "=r"(r0), "=r"(r1), "=r"(r2), "=r"(r3) : "r"(addr));
}
__device__ __forceinline__ void mma16816(float& d0, float& d1, float& d2, float& d3,
                                         uint32_t a0, uint32_t a1, uint32_t a2, uint32_t a3,
                                         uint32_t b0, uint32_t b1) {
    asm volatile("mma.sync.aligned.m16n8k16.row.col.f32.bf16.bf16.f32 "
                 "{%0,%1,%2,%3}, {%4,%5,%6,%7}, {%8,%9}, {%0,%1,%2,%3};"
                 : "+f"(d0), "+f"(d1), "+f"(d2), "+f"(d3)
                 : "r"(a0), "r"(a1), "r"(a2), "r"(a3), "r"(b0), "r"(b1));
}
__device__ __forceinline__ void mma16816h(float& d0, float& d1, float& d2, float& d3,
                                          uint32_t a0, uint32_t a1, uint32_t a2, uint32_t a3,
                                          uint32_t b0, uint32_t b1) {
    asm volatile("mma.sync.aligned.m16n8k16.row.col.f32.f16.f16.f32 "
                 "{%0,%1,%2,%3}, {%4,%5,%6,%7}, {%8,%9}, {%0,%1,%2,%3};"
                 : "+f"(d0), "+f"(d1), "+f"(d2), "+f"(d3)
                 : "r"(a0), "r"(a1), "r"(a2), "r"(a3), "r"(b0), "r"(b1));
}

__device__ __forceinline__ float gelu_exact(float x) {
    return 0.5f * x * (1.0f + erff(x * 0.70710678118654752f));
}

// swizzled 64B-row offset: row r, 16B chunk c (0..3)
__device__ __forceinline__ uint32_t swz(uint32_t r, uint32_t c) {
    return r * 64 + ((c ^ ((r >> 1) & 3)) << 4);
}

// pack 4 floats into bf16 hi/lo pairs (8B each)
__device__ __forceinline__ void split4(float o0, float o1, float o2, float o3,
                                       uint2& hv, uint2& lv) {
    __nv_bfloat162 h01 = __floats2bfloat162_rn(o0, o1);
    __nv_bfloat162 h23 = __floats2bfloat162_rn(o2, o3);
    float e0 = o0 - __bfloat162float(h01.x), e1 = o1 - __bfloat162float(h01.y);
    float e2 = o2 - __bfloat162float(h23.x), e3 = o3 - __bfloat162float(h23.y);
    __nv_bfloat162 l01 = __floats2bfloat162_rn(e0, e1);
    __nv_bfloat162 l23 = __floats2bfloat162_rn(e2, e3);
    hv = make_uint2(*(uint32_t*)&h01, *(uint32_t*)&h23);
    lv = make_uint2(*(uint32_t*)&l01, *(uint32_t*)&l23);
}

// ---------------- TM64 HMMA GEMM (bf16x3): CTA 64x128, BK=32, 4-stage ----------------
#define S64_AHI 0
#define S64_ALO 4096
#define S64_BHI 8192
#define S64_BLO 16384
#define STAGE64 24576
#define GEMM64_SMEM (4*STAGE64)

template<int MODE>
__global__ __launch_bounds__(256, 2)
void gemm_hmma64(const __nv_bfloat16* __restrict__ Ahi, const __nv_bfloat16* __restrict__ Alo,
                 const __nv_bfloat16* __restrict__ Bhi, const __nv_bfloat16* __restrict__ Blo,
                 const float* __restrict__ bias, float* __restrict__ C,
                 __nv_bfloat16* __restrict__ Chi, __nv_bfloat16* __restrict__ Clo,
                 int N, int K) {
    extern __shared__ char smem[];
    const uint32_t sb = smem_u32(smem);
    const int tid  = threadIdx.x;
    const int wid  = tid >> 5;
    const int lane = tid & 31;
    const int wrow = wid & 1;
    const int wcol = wid >> 1;
    const int bm = blockIdx.y << 6;
    const long bn = (long)blockIdx.x << 7;
    const int nc = K >> 5;

    const uint32_t rt = tid >> 2, ct = tid & 3;
    const uint32_t soA  = swz(rt, ct);
    const uint32_t soB1 = swz(rt + 64, ct);

    #define LOAD_FULL(kc, s) do {                                                      \
        uint32_t st_ = sb + (s) * STAGE64;                                              \
        size_t ga  = ((size_t)(bm + rt) * K + (kc) * 32 + ct * 8) * 2;                  \
        size_t gb0 = ((size_t)(bn + rt) * K + (kc) * 32 + ct * 8) * 2;                  \
        size_t gb1 = ((size_t)(bn + rt + 64) * K + (kc) * 32 + ct * 8) * 2;             \
        cp16(st_ + S64_AHI + soA,  (const char*)Ahi + ga);                              \
        cp16(st_ + S64_ALO + soA,  (const char*)Alo + ga);                              \
        cp16(st_ + S64_BHI + soA,  (const char*)Bhi + gb0);                             \
        cp16(st_ + S64_BLO + soA,  (const char*)Blo + gb0);                             \
        cp16(st_ + S64_BHI + soB1, (const char*)Bhi + gb1);                             \
        cp16(st_ + S64_BLO + soB1, (const char*)Blo + gb1);                             \
    } while (0)

    const int lane8 = lane & 7, sub = lane >> 3;
    const uint32_t ra = wrow * 32 + (sub & 1) * 8 + lane8;
    const uint32_t aks0 = swz(ra, (sub >> 1));
    const uint32_t aks1 = swz(ra, (sub >> 1) + 2);
    const uint32_t rb = wcol * 32 + lane8;
    const uint32_t boffs = swz(rb, sub);

    float acc[2][4][4];
    #pragma unroll
    for (int i = 0; i < 2; i++)
        #pragma unroll
        for (int j = 0; j < 4; j++)
            #pragma unroll
            for (int e = 0; e < 4; e++) acc[i][j][e] = 0.f;

    int slot = 0;
    LOAD_FULL(0, 0); cp_commit();
    LOAD_FULL(1, 1); cp_commit();
    LOAD_FULL(2, 2); cp_commit();
    for (int it = 0; it < nc; it++) {
        cp_wait<2>();
        __syncthreads();
        if (it + 3 < nc) {
            int ns = slot + 3; if (ns >= 4) ns -= 4;
            LOAD_FULL(it + 3, ns);
        }
        cp_commit();
        const uint32_t st = sb + slot * STAGE64;

        uint32_t bh[4][4], bl[4][4], ah[2][2][4], al[2][2][4];
        #pragma unroll
        for (int nj = 0; nj < 4; nj++) {
            ldsm4(bh[nj][0], bh[nj][1], bh[nj][2], bh[nj][3], st + S64_BHI + boffs + nj * 512);
            ldsm4(bl[nj][0], bl[nj][1], bl[nj][2], bl[nj][3], st + S64_BLO + boffs + nj * 512);
        }
        #pragma unroll
        for (int mi = 0; mi < 2; mi++) {
            ldsm4(ah[0][mi][0], ah[0][mi][1], ah[0][mi][2], ah[0][mi][3],
                  st + S64_AHI + aks0 + mi * 1024);
            ldsm4(ah[1][mi][0], ah[1][mi][1], ah[1][mi][2], ah[1][mi][3],
                  st + S64_AHI + aks1 + mi * 1024);
            ldsm4(al[0][mi][0], al[0][mi][1], al[0][mi][2], al[0][mi][3],
                  st + S64_ALO + aks0 + mi * 1024);
            ldsm4(al[1][mi][0], al[1][mi][1], al[1][mi][2], al[1][mi][3],
                  st + S64_ALO + aks1 + mi * 1024);
        }
        #pragma unroll
        for (int ks = 0; ks < 2; ks++) {
            #pragma unroll
            for (int mi = 0; mi < 2; mi++)
                #pragma unroll
                for (int nj = 0; nj < 4; nj++)
                    mma16816(acc[mi][nj][0], acc[mi][nj][1], acc[mi][nj][2], acc[mi][nj][3],
                             ah[ks][mi][0], ah[ks][mi][1], ah[ks][mi][2], ah[ks][mi][3],
                             bh[nj][ks * 2], bh[nj][ks * 2 + 1]);
            #pragma unroll
            for (int mi = 0; mi < 2; mi++)
                #pragma unroll
                for (int nj = 0; nj < 4; nj++)
                    mma16816(acc[mi][nj][0], acc[mi][nj][1], acc[mi][nj][2], acc[mi][nj][3],
                             ah[ks][mi][0], ah[ks][mi][1], ah[ks][mi][2], ah[ks][mi][3],
                             bl[nj][ks * 2], bl[nj][ks * 2 + 1]);
            #pragma unroll
            for (int mi = 0; mi < 2; mi++)
                #pragma unroll
                for (int nj = 0; nj < 4; nj++)
                    mma16816(acc[mi][nj][0], acc[mi][nj][1], acc[mi][nj][2], acc[mi][nj][3],
                             al[ks][mi][0], al[ks][mi][1], al[ks][mi][2], al[ks][mi][3],
                             bh[nj][ks * 2], bh[nj][ks * 2 + 1]);
        }
        if (++slot == 4) slot = 0;
    }

    const int gr = lane >> 2;
    const int gc = (lane & 3) * 2;
    #pragma unroll
    for (int mi = 0; mi < 2; mi++) {
        size_t row0 = (size_t)(bm + wrow * 32 + mi * 16 + gr) * N;
        size_t row1 = row0 + (size_t)8 * N;
        #pragma unroll
        for (int nj = 0; nj < 4; nj++) {
            long c = bn + wcol * 32 + nj * 8 + gc;
            float b0 = bias[c], b1 = bias[c + 1];
            if (MODE == 0) {
                C[row0 + c]     = acc[mi][nj][0] + b0;
                C[row0 + c + 1] = acc[mi][nj][1] + b1;
                C[row1 + c]     = acc[mi][nj][2] + b0;
                C[row1 + c + 1] = acc[mi][nj][3] + b1;
            } else {
                float v0 = gelu_exact(acc[mi][nj][0] + b0);
                float v1 = gelu_exact(acc[mi][nj][1] + b1);
                float v2 = gelu_exact(acc[mi][nj][2] + b0);
                float v3 = gelu_exact(acc[mi][nj][3] + b1);
                __nv_bfloat162 hp0 = __floats2bfloat162_rn(v0, v1);
                __nv_bfloat162 hp1 = __floats2bfloat162_rn(v2, v3);
                float e0 = v0 - __bfloat162float(hp0.x), e1 = v1 - __bfloat162float(hp0.y);
                float e2 = v2 - __bfloat162float(hp1.x), e3 = v3 - __bfloat162float(hp1.y);
                __nv_bfloat162 lp0 = __floats2bfloat162_rn(e0, e1);
                __nv_bfloat162 lp1 = __floats2bfloat162_rn(e2, e3);
                *(uint32_t*)(Chi + row0 + c) = *(uint32_t*)&hp0;
                *(uint32_t*)(Clo + row0 + c) = *(uint32_t*)&lp0;
                *(uint32_t*)(Chi + row1 + c) = *(uint32_t*)&hp1;
                *(uint32_t*)(Clo + row1 + c) = *(uint32_t*)&lp1;
            }
        }
    }
    #undef LOAD_FULL
}

// ---------------- fp16 single-term GEMM (LM head), 4-stage ----------------
#define F_TA 0
#define F_TB 8192
#define F_STAGE 16384
#define F16_SMEM (4*F_STAGE)

__global__ __launch_bounds__(256, 2)
void gemm_f16(const __half* __restrict__ A, const __half* __restrict__ B,
              const float* __restrict__ bias, float* __restrict__ C, int N, int K) {
    extern __shared__ char smem[];
    const uint32_t sb = smem_u32(smem);
    const int tid  = threadIdx.x;
    const int wid  = tid >> 5;
    const int lane = tid & 31;
    const int wrow = wid & 1;
    const int wcol = wid >> 1;
    const int bm = blockIdx.x << 7;
    const long bn = (long)blockIdx.y << 7;
    const int nc = K >> 5;

    const uint32_t r0t = tid >> 2, c0t = tid & 3;
    const uint32_t r1t = r0t + 64;
    const uint32_t so0 = swz(r0t, c0t);
    const uint32_t so1 = swz(r1t, c0t);

    #define LOAD_STAGE_F(kc, s) do {                                                   \
        uint32_t st_ = sb + (s) * F_STAGE;                                              \
        {                                                                               \
            size_t ga = ((size_t)(bm + r0t) * K + (kc) * 32 + c0t * 8) * 2;             \
            size_t gb = ((size_t)(bn + r0t) * K + (kc) * 32 + c0t * 8) * 2;             \
            cp16(st_ + F_TA + so0, (const char*)A + ga);                                \
            cp16(st_ + F_TB + so0, (const char*)B + gb);                                \
        }                                                                               \
        {                                                                               \
            size_t ga = ((size_t)(bm + r1t) * K + (kc) * 32 + c0t * 8) * 2;             \
            size_t gb = ((size_t)(bn + r1t) * K + (kc) * 32 + c0t * 8) * 2;             \
            cp16(st_ + F_TA + so1, (const char*)A + ga);                                \
            cp16(st_ + F_TB + so1, (const char*)B + gb);                                \
        }                                                                               \
    } while (0)

    LOAD_STAGE_F(0, 0); cp_commit();
    LOAD_STAGE_F(1, 1); cp_commit();
    LOAD_STAGE_F(2, 2); cp_commit();

    const int lane8 = lane & 7, sub = lane >> 3;
    const uint32_t ra = wrow * 64 + (sub & 1) * 8 + lane8;
    const uint32_t aks0 = swz(ra, (sub >> 1));
    const uint32_t aks1 = swz(ra, (sub >> 1) + 2);
    const uint32_t rb = wcol * 32 + lane8;
    const uint32_t boffs = swz(rb, sub);

    float acc[4][4][4];
    #pragma unroll
    for (int i = 0; i < 4; i++)
        #pragma unroll
        for (int j = 0; j < 4; j++)
            #pragma unroll
            for (int e = 0; e < 4; e++) acc[i][j][e] = 0.f;

    int slot = 0;
    for (int it = 0; it < nc; it++) {
        cp_wait<2>();
        __syncthreads();
        if (it + 3 < nc) {
            int ns = slot + 3; if (ns >= 4) ns -= 4;
            LOAD_STAGE_F(it + 3, ns);
        }
        cp_commit();
        const uint32_t st = sb + slot * F_STAGE;

        uint32_t bf[4][4];
        #pragma unroll
        for (int nj = 0; nj < 4; nj++)
            ldsm4(bf[nj][0], bf[nj][1], bf[nj][2], bf[nj][3], st + F_TB + boffs + nj * 512);
        #pragma unroll
        for (int ks = 0; ks < 2; ks++) {
            const uint32_t ao = (ks == 0) ? aks0 : aks1;
            uint32_t a[4][4];
            #pragma unroll
            for (int mi = 0; mi < 4; mi++)
                ldsm4(a[mi][0], a[mi][1], a[mi][2], a[mi][3], st + F_TA + ao + mi * 1024);
            #pragma unroll
            for (int mi = 0; mi < 4; mi++)
                #pragma unroll
                for (int nj = 0; nj < 4; nj++)
                    mma16816h(acc[mi][nj][0], acc[mi][nj][1], acc[mi][nj][2], acc[mi][nj][3],
                              a[mi][0], a[mi][1], a[mi][2], a[mi][3],
                              bf[nj][ks * 2], bf[nj][ks * 2 + 1]);
        }
        if (++slot == 4) slot = 0;
    }

    const int gr = lane >> 2;
    const int gc = (lane & 3) * 2;
    #pragma unroll
    for (int mi = 0; mi < 4; mi++) {
        size_t row0 = (size_t)(bm + wrow * 64 + mi * 16 + gr) * N;
        size_t row1 = row0 + (size_t)8 * N;
        #pragma unroll
        for (int nj = 0; nj < 4; nj++) {
            long c = bn + wcol * 32 + nj * 8 + gc;
            if (c < N) {
                C[row0 + c] = acc[mi][nj][0] + bias[c];
                C[row1 + c] = acc[mi][nj][2] + bias[c];
            }
            if (c + 1 < N) {
                C[row0 + c + 1] = acc[mi][nj][1] + bias[c + 1];
                C[row1 + c + 1] = acc[mi][nj][3] + bias[c + 1];
            }
        }
    }
    #undef LOAD_STAGE_F
}

// ---------------- weight transpose + split (bf16 hi/lo), 16B stores ----------------
// QKV==2: V-only per-(layer,head): ob = layer*H*H + head*64*H
template<int QKV>
__global__ __launch_bounds__(256)
void transpose_split(const float* __restrict__ src0,
                     __nv_bfloat16* __restrict__ hi, __nv_bfloat16* __restrict__ lo,
                     int R, int C) {
    __shared__ float t[128][33];
    int z = blockIdx.z;
    const float* src = src0;
    const size_t ib = (size_t)z * R * C;
    size_t ob;
    if (QKV == 2) ob = (size_t)(z >> 4) * (H * H) + (size_t)(z & 15) * (64 * H);
    else          ob = ib;
    const int r0 = blockIdx.y * 128, c0 = blockIdx.x * 32;
    const int cc = threadIdx.x & 31, rb = threadIdx.x >> 5;
    const bool cok = (c0 + cc) < C;
    #pragma unroll
    for (int p = 0; p < 16; p++) {
        int rr = rb + p * 8;
        t[rr][cc] = cok ? src[ib + (size_t)(r0 + rr) * C + c0 + cc] : 0.f;
    }
    __syncthreads();
    const int oc2 = threadIdx.x >> 4;
    const int r8  = (threadIdx.x & 15) * 8;
    #pragma unroll
    for (int cp = 0; cp < 2; cp++) {
        int col = cp * 16 + oc2;
        if (c0 + col < C) {
            uint32_t hw[4], lw[4];
            #pragma unroll
            for (int i = 0; i < 4; i++) {
                float f0 = t[r8 + 2 * i][col], f1 = t[r8 + 2 * i + 1][col];
                __nv_bfloat162 hp = __floats2bfloat162_rn(f0, f1);
                hw[i] = *(uint32_t*)&hp;
                float e0 = f0 - __bfloat162float(hp.x);
                float e1 = f1 - __bfloat162float(hp.y);
                __nv_bfloat162 lp = __floats2bfloat162_rn(e0, e1);
                lw[i] = *(uint32_t*)&lp;
            }
            size_t obase = ob + (size_t)(c0 + col) * R + r0 + r8;
            *(uint4*)(hi + obase) = make_uint4(hw[0], hw[1], hw[2], hw[3]);
            *(uint4*)(lo + obase) = make_uint4(lw[0], lw[1], lw[2], lw[3]);
        }
    }
}

// ---------------- fp16 weight transpose (LM head), 16B stores ----------------
__global__ __launch_bounds__(256)
void transpose_f16(const float* __restrict__ src, __half* __restrict__ out, int R, int C) {
    __shared__ float t[128][33];
    const int r0 = blockIdx.y * 128, c0 = blockIdx.x * 32;
    const int cc = threadIdx.x & 31, rb = threadIdx.x >> 5;
    const bool cok = (c0 + cc) < C;
    #pragma unroll
    for (int p = 0; p < 16; p++) {
        int rr = rb + p * 8;
        t[rr][cc] = cok ? src[(size_t)(r0 + rr) * C + c0 + cc] : 0.f;
    }
    __syncthreads();
    const int oc2 = threadIdx.x >> 4;
    const int r8  = (threadIdx.x & 15) * 8;
    #pragma unroll
    for (int cp = 0; cp < 2; cp++) {
        int col = cp * 16 + oc2;
        if (c0 + col < C) {
            uint32_t hw[4];
            #pragma unroll
            for (int i = 0; i < 4; i++) {
                __half2 hp = __floats2half2_rn(t[r8 + 2 * i][col], t[r8 + 2 * i + 1][col]);
                hw[i] = *(uint32_t*)&hp;
            }
            size_t obase = (size_t)(c0 + col) * R + r0 + r8;
            *(uint4*)(out + obase) = make_uint4(hw[0], hw[1], hw[2], hw[3]);
        }
    }
}

// ---------------- embedding: x = emb[tok] + pos, + split ----------------
__global__ void embed_kernel(const int* __restrict__ tok, const float* __restrict__ emb,
                             const float* __restrict__ pos, float* __restrict__ x,
                             __nv_bfloat16* __restrict__ hi, __nv_bfloat16* __restrict__ lo) {
    int i4 = blockIdx.x * 256 + threadIdx.x;
    int e = i4 * 4;
    int s = e >> 10, h = e & 1023;
    float4 ev = *(const float4*)(emb + (size_t)tok[s] * H + h);
    float4 pv = *(const float4*)(pos + e);
    float o0 = ev.x + pv.x, o1 = ev.y + pv.y, o2 = ev.z + pv.z, o3 = ev.w + pv.w;
    *(float4*)(x + e) = make_float4(o0, o1, o2, o3);
    uint2 hv, lv;
    split4(o0, o1, o2, o3, hv, lv);
    *(uint2*)(hi + e) = hv;
    *(uint2*)(lo + e) = lv;
}

// ---------------- qwk: q_last = x[S-1]·Wq[head];  w~ = Wk[head]·q_last ----------------
__global__ __launch_bounds__(256)
void qwk_kernel(const float* __restrict__ x, const float* __restrict__ Wq,
                const float* __restrict__ Wk, float* __restrict__ wt) {
    __shared__ float qs[64];
    __shared__ float red[256];
    const int h = blockIdx.x, tid = threadIdx.x;
    const float* xr = x + (size_t)(S - 1) * H;
    const int d = tid & 63, qr = tid >> 6;
    const float* wq = Wq + (size_t)h * H * DH;
    float acc = 0.f;
    for (int j = qr * 256; j < qr * 256 + 256; j++)
        acc = fmaf(xr[j], wq[(size_t)j * DH + d], acc);
    red[tid] = acc; __syncthreads();
    if (tid < 64) qs[tid] = red[tid] + red[tid + 64] + red[tid + 128] + red[tid + 192];
    __syncthreads();
    const float* wk = Wk + (size_t)h * H * DH;
    for (int j = tid; j < H; j += 256) {
        float a = 0.f;
        #pragma unroll
        for (int d2 = 0; d2 < 64; d2++) a = fmaf(wk[(size_t)j * DH + d2], qs[d2], a);
        wt[h * H + j] = a;
    }
}

// ---------------- sv: s[t,h] = x[t]·w~[h]  (warp per token, coalesced) ----------------
__global__ __launch_bounds__(256)
void sv_kernel(const float* __restrict__ x, const float* __restrict__ wt,
               float* __restrict__ s) {
    const int warp = threadIdx.x >> 5, lane = threadIdx.x & 31;
    const int t = blockIdx.x * 8 + warp;
    const float* xr = x + (size_t)t * H;
    float acc[NH];
    #pragma unroll
    for (int h = 0; h < NH; h++) acc[h] = 0.f;
    #pragma unroll
    for (int jb = 0; jb < H; jb += 128) {
        int j = jb + lane * 4;
        float4 xv = *(const float4*)(xr + j);
        #pragma unroll
        for (int h = 0; h < NH; h++) {
            float4 wv = *(const float4*)(wt + h * H + j);
            acc[h] += xv.x * wv.x + xv.y * wv.y + xv.z * wv.z + xv.w * wv.w;
        }
    }
    #pragma unroll
    for (int h = 0; h < NH; h++) {
        #pragma unroll
        for (int o = 16; o > 0; o >>= 1)
            acc[h] += __shfl_xor_sync(0xFFFFFFFFu, acc[h], o);
    }
    if (lane < NH) s[(size_t)t * NH + lane] = acc[lane];
}

// ---------------- part[seg,col] = sum of 64 V rows (coalesced) ----------------
__global__ void part_kernel(const float* __restrict__ v, float* __restrict__ part) {
    int col = blockIdx.y * 256 + threadIdx.x;
    int seg = blockIdx.x;
    float a = 0.f;
    for (int r = 0; r < 64; r++) a += v[(size_t)(seg * 64 + r) * H + col];
    part[seg * 1024 + col] = a;
}

// ---------------- alast[h,d] = 0.125 * sum_t s[t,h]·v[t, h*64+d] ----------------
__global__ __launch_bounds__(256)
void alast_kernel(const float* __restrict__ s, const float* __restrict__ v,
                  float* __restrict__ alast) {
    __shared__ float red[256];
    const int h = blockIdx.x, tid = threadIdx.x;
    const int d = tid & 63, p = tid >> 6;
    float a0 = 0.f, a1 = 0.f;
    for (int t = p * 512; t < p * 512 + 512; t += 2) {
        a0 = fmaf(s[(size_t)t * NH + h],       v[(size_t)t * H + h * 64 + d],       a0);
        a1 = fmaf(s[(size_t)(t + 1) * NH + h], v[(size_t)(t + 1) * H + h * 64 + d], a1);
    }
    red[tid] = a0 + a1; __syncthreads();
    if (tid < 64)
        alast[h * 64 + tid] = 0.125f * (red[tid] + red[tid + 64] + red[tid + 128] + red[tid + 192]);
}

// ---------------- attn: att = -1e9*suffix(V); row S-1 = alast; emit hi/lo ----------------
__global__ __launch_bounds__(256)
void attn_sfx(const float* __restrict__ v, const float* __restrict__ part,
              const float* __restrict__ alast,
              __nv_bfloat16* __restrict__ ahi, __nv_bfloat16* __restrict__ alo) {
    __shared__ float Vs[64][65];
    __shared__ float red[4][64];
    const int head = blockIdx.y;
    const int bidx = blockIdx.x;
    const int s0 = bidx * 64;
    const int tid = threadIdx.x;
    for (int i = tid; i < 4096; i += 256) {
        int r = i >> 6, c = i & 63;
        Vs[r][c] = v[(size_t)(s0 + r) * H + head * DH + c];
    }
    __syncthreads();
    const int vc = tid & 63, q = tid >> 6;
    {
        float qs = 0.f;
        #pragma unroll
        for (int r = 0; r < 16; r++) qs += Vs[q * 16 + r][vc];
        red[q][vc] = qs;
    }
    __syncthreads();
    {
        float run = 0.f;
        for (int b2 = bidx + 1; b2 < 32; b2++)
            run += part[(size_t)b2 * 1024 + head * DH + vc];
        for (int q2 = q + 1; q2 < 4; q2++) run += red[q2][vc];
        for (int r = q * 16 + 15; r >= q * 16; r--) {
            float tmpv = Vs[r][vc];
            Vs[r][vc] = run;
            run += tmpv;
        }
    }
    __syncthreads();
    #pragma unroll
    for (int k = 0; k < 4; k++) {
        int i = tid + k * 256;
        int r = i >> 4, c4 = (i & 15) * 4;
        float o0, o1, o2, o3;
        if (bidx == 31 && r == 63) {
            o0 = alast[head * 64 + c4];     o1 = alast[head * 64 + c4 + 1];
            o2 = alast[head * 64 + c4 + 2]; o3 = alast[head * 64 + c4 + 3];
        } else {
            o0 = -1e9f * Vs[r][c4];     o1 = -1e9f * Vs[r][c4 + 1];
            o2 = -1e9f * Vs[r][c4 + 2]; o3 = -1e9f * Vs[r][c4 + 3];
        }
        size_t sb = (size_t)(s0 + r) * H + head * DH + c4;
        uint2 hv, lv;
        split4(o0, o1, o2, o3, hv, lv);
        *(uint2*)(ahi + sb) = hv;
        *(uint2*)(alo + sb) = lv;
    }
}

// ---------------- LayerNorm (+residual) + fused split, warp-shuffle reduce ----------------
template<bool ADD, bool WF32, int OUTK>
__global__ __launch_bounds__(256)
void ln_kernel(const float* __restrict__ t, const float* __restrict__ xin,
               const float* __restrict__ g, const float* __restrict__ b,
               float* __restrict__ outf,
               __nv_bfloat16* __restrict__ hi, __nv_bfloat16* __restrict__ lo,
               __half* __restrict__ outh) {
    const int row = blockIdx.x;
    const int tid = threadIdx.x;
    const int wid = tid >> 5, lane = tid & 31;
    float4 v = *(const float4*)(t + (size_t)row * H + tid * 4);
    __shared__ float wred[8];
    __shared__ float stat[2];

    float s = v.x + v.y + v.z + v.w;
    #pragma unroll
    for (int o = 16; o > 0; o >>= 1) s += __shfl_xor_sync(0xFFFFFFFFu, s, o);
    if (lane == 0) wred[wid] = s;
    __syncthreads();
    if (tid == 0) {
        float tot = 0.f;
        #pragma unroll
        for (int w = 0; w < 8; w++) tot += wred[w];
        stat[0] = tot * (1.0f / H);
    }
    __syncthreads();
    float mean = stat[0];

    float dx = v.x - mean, dy = v.y - mean, dz = v.z - mean, dw = v.w - mean;
    float vs = dx * dx + dy * dy + dz * dz + dw * dw;
    #pragma unroll
    for (int o = 16; o > 0; o >>= 1) vs += __shfl_xor_sync(0xFFFFFFFFu, vs, o);
    if (lane == 0) wred[wid] = vs;
    __syncthreads();
    if (tid == 0) {
        float tot = 0.f;
        #pragma unroll
        for (int w = 0; w < 8; w++) tot += wred[w];
        stat[1] = rsqrtf(tot * (1.0f / H) + 1e-5f);
    }
    __syncthreads();
    float rstd = stat[1];

    int h = tid * 4;
    float4 gv = *(const float4*)(g + h);
    float4 bv = *(const float4*)(b + h);
    float o0 = dx * rstd * gv.x + bv.x;
    float o1 = dy * rstd * gv.y + bv.y;
    float o2 = dz * rstd * gv.z + bv.z;
    float o3 = dw * rstd * gv.w + bv.w;
    if (ADD) {
        float4 xv = *(const float4*)(xin + (size_t)row * H + h);
        o0 += xv.x; o1 += xv.y; o2 += xv.z; o3 += xv.w;
    }
    if (WF32) *(float4*)(outf + (size_t)row * H + h) = make_float4(o0, o1, o2, o3);
    if (OUTK == 0) {
        uint2 hv, lv;
        split4(o0, o1, o2, o3, hv, lv);
        *(uint2*)(hi + (size_t)row * H + h) = hv;
        *(uint2*)(lo + (size_t)row * H + h) = lv;
    } else {
        __half2 h0 = __floats2half2_rn(o0, o1);
        __half2 h1 = __floats2half2_rn(o2, o3);
        *(uint2*)(outh + (size_t)row * H + h) = make_uint2(*(uint32_t*)&h0, *(uint32_t*)&h1);
    }
}

// ---------------- launch ----------------
extern "C" void kernel_launch(void* const* d_in, const int* in_sizes, int n_in,
                              void* d_out, int out_size) {
    const int*   tokens = (const int*)  d_in[0];
    const float* emb    = (const float*)d_in[1];
    const float* pos    = (const float*)d_in[2];
    const float* Wq     = (const float*)d_in[3];
    const float* Wk     = (const float*)d_in[4];
    const float* Wv     = (const float*)d_in[5];
    const float* Wp     = (const float*)d_in[6];
    const float* bp     = (const float*)d_in[7];
    const float* W1     = (const float*)d_in[8];
    const float* b1     = (const float*)d_in[9];
    const float* W2     = (const float*)d_in[10];
    const float* b2     = (const float*)d_in[11];
    const float* ln_g   = (const float*)d_in[12];
    const float* ln_b   = (const float*)d_in[13];
    const float* Wlm    = (const float*)d_in[14];
    const float* blm    = (const float*)d_in[15];
    float* out = (float*)d_out;
    const int Vv = in_sizes[15];

    float *x, *tmp, *res, *v, *part, *sbuf, *wt, *al, *zb;
    __nv_bfloat16 *ahi, *alo, *bhi, *blo;
    __nv_bfloat16 *btv_hi, *btv_lo, *btp_hi, *btp_lo;
    __nv_bfloat16 *bt1_hi, *bt1_lo, *bt2_hi, *bt2_lo;
    __half *wlm, *xf16;
    cudaGetSymbolAddress((void**)&x, g_x);       cudaGetSymbolAddress((void**)&tmp, g_tmp);
    cudaGetSymbolAddress((void**)&res, g_res);   cudaGetSymbolAddress((void**)&v, g_v);
    cudaGetSymbolAddress((void**)&part, g_part); cudaGetSymbolAddress((void**)&sbuf, g_s);
    cudaGetSymbolAddress((void**)&wt, g_wt);     cudaGetSymbolAddress((void**)&al, g_alast);
    cudaGetSymbolAddress((void**)&zb, g_zb);
    cudaGetSymbolAddress((void**)&ahi, g_ahi);   cudaGetSymbolAddress((void**)&alo, g_alo);
    cudaGetSymbolAddress((void**)&bhi, g_bhi);   cudaGetSymbolAddress((void**)&blo, g_blo);
    cudaGetSymbolAddress((void**)&btv_hi, g_btv_hi); cudaGetSymbolAddress((void**)&btv_lo, g_btv_lo);
    cudaGetSymbolAddress((void**)&btp_hi, g_btp_hi); cudaGetSymbolAddress((void**)&btp_lo, g_btp_lo);
    cudaGetSymbolAddress((void**)&bt1_hi, g_bt1_hi); cudaGetSymbolAddress((void**)&bt1_lo, g_bt1_lo);
    cudaGetSymbolAddress((void**)&bt2_hi, g_bt2_hi); cudaGetSymbolAddress((void**)&bt2_lo, g_bt2_lo);
    cudaGetSymbolAddress((void**)&wlm, g_wlm_f16);   cudaGetSymbolAddress((void**)&xf16, g_xf_f16);

    cudaFuncSetAttribute(gemm_hmma64<0>, cudaFuncAttributeMaxDynamicSharedMemorySize, GEMM64_SMEM);
    cudaFuncSetAttribute(gemm_hmma64<1>, cudaFuncAttributeMaxDynamicSharedMemorySize, GEMM64_SMEM);
    cudaFuncSetAttribute(gemm_f16, cudaFuncAttributeMaxDynamicSharedMemorySize, F16_SMEM);

    dim3 tb(256);
    // idx0: embed
    embed_kernel<<<(S * H) / 1024, 256>>>(tokens, emb, pos, x, ahi, alo);
    // idx1: V weight transpose only (Q/K weights are consumed raw in qwk_kernel)
    transpose_split<2><<<dim3(2, 8, NLAYERS * NH), tb>>>(Wv, btv_hi, btv_lo, H, DH);
    // idx2: proj weights
    transpose_split<0><<<dim3(32, 8, NLAYERS), tb>>>(Wp, btp_hi, btp_lo, H, H);
    // idx3: V GEMM layer 0 (profile target)
    gemm_hmma64<0><<<dim3(8, 32), 256, GEMM64_SMEM>>>(ahi, alo, btv_hi, btv_lo,
                                                      zb, v, nullptr, nullptr, H, H);
    // remaining weight transposes
    transpose_split<0><<<dim3(128, 8, NLAYERS), tb>>>(W1, bt1_hi, bt1_lo, H, FF);
    transpose_split<0><<<dim3(32, 32, NLAYERS), tb>>>(W2, bt2_hi, bt2_lo, FF, H);
    transpose_f16<<<dim3((Vv + 31) / 32, 8), tb>>>(Wlm, wlm, H, Vv);

    for (int l = 0; l < NLAYERS; l++) {
        size_t oV = (size_t)l * H * H;
        size_t oH = (size_t)l * H * H;
        size_t oF = (size_t)l * H * FF;
        size_t oW = (size_t)l * NH * H * DH;

        if (l > 0)
            gemm_hmma64<0><<<dim3(8, 32), 256, GEMM64_SMEM>>>(ahi, alo, btv_hi + oV, btv_lo + oV,
                                                              zb, v, nullptr, nullptr, H, H);
        qwk_kernel<<<NH, 256>>>(x, Wq + oW, Wk + oW, wt);
        sv_kernel<<<S / 8, 256>>>(x, wt, sbuf);
        part_kernel<<<dim3(32, 4), 256>>>(v, part);
        alast_kernel<<<NH, 256>>>(sbuf, v, al);
        attn_sfx<<<dim3(32, NH), 256>>>(v, part, al, ahi, alo);

        gemm_hmma64<0><<<dim3(8, 32), 256, GEMM64_SMEM>>>(ahi, alo, btp_hi + oH, btp_lo + oH,
                                                          bp + (size_t)l * H, tmp, nullptr, nullptr,
                                                          H, H);
        ln_kernel<true, true, 0><<<S, 256>>>(tmp, x, ln_g, ln_b, res, ahi, alo, nullptr);

        gemm_hmma64<1><<<dim3(32, 32), 256, GEMM64_SMEM>>>(ahi, alo, bt1_hi + oF, bt1_lo + oF,
                                                           b1 + (size_t)l * FF, nullptr, bhi, blo,
                                                           FF, H);
        gemm_hmma64<0><<<dim3(8, 32), 256, GEMM64_SMEM>>>(bhi, blo, bt2_hi + oF, bt2_lo + oF,
                                                          b2 + (size_t)l * H, tmp, nullptr, nullptr,
                                                          H, FF);
        ln_kernel<true, true, 0><<<S, 256>>>(tmp, res, ln_g, ln_b, x, ahi, alo, nullptr);
    }

    // final LN -> fp16, LM head in fp16 HMMA
    ln_kernel<false, false, 1><<<S, 256>>>(x, nullptr, ln_g, ln_b, nullptr, nullptr, nullptr, xf16);
    gemm_f16<<<dim3(16, VPAD / 128), 256, F16_SMEM>>>(xf16, wlm, blm, out, Vv, H);
}